// round 1
// baseline (speedup 1.0000x reference)
#include <cuda_runtime.h>
#include <cstdint>

#define N_NODES 100000
#define N_EDGES 1600000
#define IN_DIM  128
#define HID     64
#define CONVOUT 124   // 2 * 62

// ---------------- scratch (static device globals; no allocs allowed) ----------
__device__ float g_t   [N_NODES * HID];   // (feat@w1)*norm
__device__ float g_agg [N_NODES * HID];   // layer-1 accumulator (init = g_t  -> self loop)
__device__ float g_h1  [N_NODES * HID];   // dropout(relu(agg*norm)) * norm   (layer-2 scatter source)
__device__ float g_agg2[N_NODES * HID];   // layer-2 accumulator (init = g_h1 -> self loop)
__device__ float g_h2  [N_NODES * HID];   // final node features
__device__ int   g_deg [N_NODES];
__device__ float g_norm[N_NODES];
__device__ float g_colsum[HID];           // column sums of h2
__device__ float g_omean[CONVOUT];        // conv(mean) + bias

// ---------------- threefry2x32 (20 rounds, JAX-compatible) --------------------
__host__ __device__ __forceinline__ void tf2x32(uint32_t k0, uint32_t k1,
                                                uint32_t& x0, uint32_t& x1) {
    uint32_t ks2 = k0 ^ k1 ^ 0x1BD11BDAu;
#define TF_R(r) { x0 += x1; x1 = (x1 << (r)) | (x1 >> (32 - (r))); x1 ^= x0; }
    x0 += k0; x1 += k1;
    TF_R(13) TF_R(15) TF_R(26) TF_R(6)   x0 += k1;  x1 += ks2 + 1u;
    TF_R(17) TF_R(29) TF_R(16) TF_R(24)  x0 += ks2; x1 += k0  + 2u;
    TF_R(13) TF_R(15) TF_R(26) TF_R(6)   x0 += k0;  x1 += k1  + 3u;
    TF_R(17) TF_R(29) TF_R(16) TF_R(24)  x0 += k1;  x1 += ks2 + 4u;
    TF_R(13) TF_R(15) TF_R(26) TF_R(6)   x0 += ks2; x1 += k0  + 5u;
#undef TF_R
}

// partitionable-mode random_bits(key, 32, shape) for flat index idx (< 2^32):
// counter = (hi=0, lo=idx); bits = y0 ^ y1. keep (u < 0.5) <=> MSB(bits)==0.
__device__ __forceinline__ bool drop_keep(uint32_t k0, uint32_t k1, uint32_t idx) {
    uint32_t x0 = 0u, x1 = idx;
    tf2x32(k0, k1, x0, x1);
    return ((x0 ^ x1) & 0x80000000u) == 0u;
}

// ---------------- kernels ------------------------------------------------------
__global__ void k_zero() {
    int i = blockIdx.x * blockDim.x + threadIdx.x;
    if (i < N_NODES) g_deg[i] = 0;
    if (i < HID) g_colsum[i] = 0.f;
}

__global__ void k_deg(const int* __restrict__ dst) {
    int e = blockIdx.x * blockDim.x + threadIdx.x;
    if (e < N_EDGES) atomicAdd(&g_deg[dst[e]], 1);
}

__global__ void k_norm() {
    int i = blockIdx.x * blockDim.x + threadIdx.x;
    if (i < N_NODES) g_norm[i] = rsqrtf((float)(g_deg[i] + 1));
}

// t = (feat @ w1) * norm ; also init agg = t (self loop).
// block: 256 threads -> 64 nodes x 64 cols tile, k chunked by 32.
__global__ void k_gemm1(const float* __restrict__ feat, const float* __restrict__ w1) {
    __shared__ float sA[64][33];
    __shared__ float sB[32][64];
    int tid = threadIdx.x;
    int nb  = blockIdx.x * 64;
    int tx  = tid & 15, ty = tid >> 4;
    float acc[4][4] = {};
#pragma unroll
    for (int kc = 0; kc < 4; kc++) {
#pragma unroll
        for (int l = 0; l < 8; l++) {
            int e = tid + l * 256;
            int nd = e >> 5, kk = e & 31;
            int gn = nb + nd;
            sA[nd][kk] = (gn < N_NODES) ? feat[(size_t)gn * IN_DIM + kc * 32 + kk] : 0.f;
        }
#pragma unroll
        for (int l = 0; l < 8; l++) {
            int e = tid + l * 256;
            int kk = e >> 6, c = e & 63;
            sB[kk][c] = w1[(kc * 32 + kk) * HID + c];
        }
        __syncthreads();
#pragma unroll
        for (int kk = 0; kk < 32; kk++) {
            float4 b = *reinterpret_cast<float4*>(&sB[kk][tx * 4]);
            float a0 = sA[ty * 4 + 0][kk], a1 = sA[ty * 4 + 1][kk];
            float a2 = sA[ty * 4 + 2][kk], a3 = sA[ty * 4 + 3][kk];
            acc[0][0] += a0 * b.x; acc[0][1] += a0 * b.y; acc[0][2] += a0 * b.z; acc[0][3] += a0 * b.w;
            acc[1][0] += a1 * b.x; acc[1][1] += a1 * b.y; acc[1][2] += a1 * b.z; acc[1][3] += a1 * b.w;
            acc[2][0] += a2 * b.x; acc[2][1] += a2 * b.y; acc[2][2] += a2 * b.z; acc[2][3] += a2 * b.w;
            acc[3][0] += a3 * b.x; acc[3][1] += a3 * b.y; acc[3][2] += a3 * b.z; acc[3][3] += a3 * b.w;
        }
        __syncthreads();
    }
#pragma unroll
    for (int i = 0; i < 4; i++) {
        int gn = nb + ty * 4 + i;
        if (gn < N_NODES) {
            float nm = g_norm[gn];
            float4 v;
            v.x = acc[i][0] * nm; v.y = acc[i][1] * nm;
            v.z = acc[i][2] * nm; v.w = acc[i][3] * nm;
            size_t off = (size_t)gn * HID + tx * 4;
            *reinterpret_cast<float4*>(&g_t[off])   = v;
            *reinterpret_cast<float4*>(&g_agg[off]) = v;
        }
    }
}

// scatter: dbuf[dst] += sbuf[src] (64 floats / edge, 16 threads x float4 / edge)
__global__ void k_scatter(const int* __restrict__ src, const int* __restrict__ dst, int layer) {
    const float* sbuf = layer ? g_h1 : g_t;
    float*       dbuf = layer ? g_agg2 : g_agg;
    long long tid = (long long)blockIdx.x * blockDim.x + threadIdx.x;
    int e = (int)(tid >> 4);
    if (e >= N_EDGES) return;
    int q = (int)(tid & 15);
    int s = __ldg(&src[e]);
    int d = __ldg(&dst[e]);
    float4 v = __ldg(reinterpret_cast<const float4*>(&sbuf[(size_t)s * HID + q * 4]));
    float* p = &dbuf[(size_t)d * HID + q * 4];
    unsigned long long gp = (unsigned long long)__cvta_generic_to_global(p);
    asm volatile("red.global.add.v4.f32 [%0], {%1,%2,%3,%4};"
                 :: "l"(gp), "f"(v.x), "f"(v.y), "f"(v.z), "f"(v.w) : "memory");
}

// h1 = dropout(relu(agg * norm), k1) * norm ; also init agg2 = h1 (self loop)
__global__ void k_fin1(uint32_t ka0, uint32_t ka1) {
    int idx = blockIdx.x * blockDim.x + threadIdx.x;   // < N*HID = 6.4M
    int i = idx >> 6;
    float nm = g_norm[i];
    float v = g_agg[idx] * nm;
    v = fmaxf(v, 0.f);
    v = drop_keep(ka0, ka1, (uint32_t)idx) ? 2.f * v : 0.f;
    v *= nm;                                            // layer-2 pre-scale h*norm
    g_h1[idx]  = v;
    g_agg2[idx] = v;
}

// h2 = dropout(relu((agg2 @ w2) * norm), k2); accumulate column sums.
// 512 threads = 8 nodes x 64 cols.
__global__ void k_fin2(const float* __restrict__ w2, uint32_t kb0, uint32_t kb1) {
    __shared__ float sW[64 * 64];
    __shared__ float sIn[8 * 64];
    __shared__ float sOut[8 * 64];
    int tid = threadIdx.x;
    int nb = blockIdx.x * 8;
#pragma unroll
    for (int l = 0; l < 8; l++) sW[tid + l * 512] = w2[tid + l * 512];
    sIn[tid] = g_agg2[(size_t)nb * HID + tid];
    __syncthreads();
    int ny = tid >> 6, c = tid & 63;
    const float* a = &sIn[ny * 64];
    float acc = 0.f;
#pragma unroll
    for (int k = 0; k < 64; k++) acc += a[k] * sW[k * 64 + c];
    int node = nb + ny;
    float v = acc * g_norm[node];
    v = fmaxf(v, 0.f);
    uint32_t idx = (uint32_t)node * HID + (uint32_t)c;
    v = drop_keep(kb0, kb1, idx) ? 2.f * v : 0.f;
    g_h2[(size_t)node * HID + c] = v;
    sOut[tid] = v;
    __syncthreads();
    if (ny == 0) {
        float s = 0.f;
#pragma unroll
        for (int l = 0; l < 8; l++) s += sOut[l * 64 + c];
        atomicAdd(&g_colsum[c], s);
    }
}

// o = conv(mean(h2)) + bias   (mean commutes with the valid conv)
__global__ void k_omean(const float* __restrict__ cw, const float* __restrict__ cb) {
    __shared__ float m[64];
    int t = threadIdx.x;
    if (t < 64) m[t] = g_colsum[t] * (1.f / (float)N_NODES);
    __syncthreads();
    if (t < CONVOUT) {
        int o = t / 62, jj = t % 62;
        g_omean[t] = cw[o * 3 + 0] * m[jj] + cw[o * 3 + 1] * m[jj + 1]
                   + cw[o * 3 + 2] * m[jj + 2] + cb[o];
    }
}

// per-node: y = conv(h2 row)+b ; radius = sqrt(sum (y - omean + 1e-6)^2); dis = clip
// 256 threads = 8 warps = 8 nodes per block
__global__ void k_final(const float* __restrict__ cw, const float* __restrict__ cb,
                        const float* __restrict__ ref, float* __restrict__ out) {
    __shared__ float sO[CONVOUT];
    int tid = threadIdx.x;
    if (tid < CONVOUT) sO[tid] = g_omean[tid];
    __syncthreads();
    int lane = tid & 31, warp = tid >> 5;
    int node = blockIdx.x * 8 + warp;
    float w00 = cw[0], w01 = cw[1], w02 = cw[2];
    float w10 = cw[3], w11 = cw[4], w12 = cw[5];
    float b0 = cb[0], b1 = cb[1];
    const float* h = &g_h2[(size_t)node * HID];
    float acc = 0.f;
#pragma unroll
    for (int l = 0; l < 4; l++) {
        int j = lane * 4 + l;
        if (j < CONVOUT) {
            float y;
            if (j < 62) y = w00 * h[j] + w01 * h[j + 1] + w02 * h[j + 2] + b0;
            else { int jj = j - 62; y = w10 * h[jj] + w11 * h[jj + 1] + w12 * h[jj + 2] + b1; }
            float d = y - sO[j] + 1e-6f;
            acc += d * d;
        }
    }
#pragma unroll
    for (int o = 16; o; o >>= 1) acc += __shfl_xor_sync(0xffffffffu, acc, o);
    if (lane == 0) {
        float r = sqrtf(acc);
        float dis = fminf(fmaxf(r - ref[0], 1e-4f), 0.9999f);
        out[node] = dis;
    }
    if (blockIdx.x == 0 && tid == 0) out[N_NODES] = ref[0];
}

// ---------------- launch -------------------------------------------------------
extern "C" void kernel_launch(void* const* d_in, const int* in_sizes, int n_in,
                              void* d_out, int out_size) {
    const float* feat = (const float*)d_in[0];
    const float* w1   = (const float*)d_in[1];
    const float* w2   = (const float*)d_in[2];
    const float* cw   = (const float*)d_in[3];
    const float* cb   = (const float*)d_in[4];
    const float* ref  = (const float*)d_in[5];
    const int*   src  = (const int*)d_in[6];
    const int*   dst  = (const int*)d_in[7];
    float* out = (float*)d_out;

    // dropout keys: key(42) = (0,42); partitionable split -> counters (0,0),(0,1)
    uint32_t ka0 = 0, ka1 = 0, kb0 = 0, kb1 = 1;
    tf2x32(0u, 42u, ka0, ka1);   // k1 = (y0, y1) of counter 0
    tf2x32(0u, 42u, kb0, kb1);   // k2 = (y0, y1) of counter 1

    k_zero<<<(N_NODES + 255) / 256, 256>>>();
    k_deg<<<(N_EDGES + 255) / 256, 256>>>(dst);
    k_norm<<<(N_NODES + 255) / 256, 256>>>();
    k_gemm1<<<(N_NODES + 63) / 64, 256>>>(feat, w1);
    {
        long long total = (long long)N_EDGES * 16;
        int blocks = (int)((total + 255) / 256);
        k_scatter<<<blocks, 256>>>(src, dst, 0);
    }
    k_fin1<<<(N_NODES * HID) / 256, 256>>>(ka0, ka1);
    {
        long long total = (long long)N_EDGES * 16;
        int blocks = (int)((total + 255) / 256);
        k_scatter<<<blocks, 256>>>(src, dst, 1);
    }
    k_fin2<<<N_NODES / 8, 512>>>(w2, kb0, kb1);
    k_omean<<<1, 128>>>(cw, cb);
    k_final<<<N_NODES / 8, 256>>>(cw, cb, ref, out);
}

// round 2
// speedup vs baseline: 1.3924x; 1.3924x over previous
#include <cuda_runtime.h>
#include <cstdint>

#define N_NODES 100000
#define N_EDGES 1600000
#define IN_DIM  128
#define HID     64
#define CONVOUT 124   // 2 * 62
#define SCAN_B  1024
#define NSCANB  ((N_NODES + SCAN_B - 1) / SCAN_B)   // 98

// ---------------- scratch (static device globals; no allocs allowed) ----------
__device__ float g_t   [N_NODES * HID];   // (feat@w1)*norm
__device__ float g_h1  [N_NODES * HID];   // dropout(relu(agg*norm))*norm (layer-2 source)
__device__ float g_agg2[N_NODES * HID];   // layer-2 aggregate (fin2 input)
__device__ float g_h2  [N_NODES * HID];   // final node features
__device__ int   g_deg [N_NODES];
__device__ int   g_cnt [N_NODES];
__device__ float g_norm[N_NODES];
__device__ int   g_rowptr[N_NODES + 1];
__device__ int   g_bsum[NSCANB];
__device__ int   g_boff[NSCANB];
__device__ int   g_csr[N_EDGES];          // src ids grouped by dst
__device__ float g_colsum[HID];
__device__ float g_omean[CONVOUT];

// ---------------- threefry2x32 (20 rounds, JAX-compatible) --------------------
__host__ __device__ __forceinline__ void tf2x32(uint32_t k0, uint32_t k1,
                                                uint32_t& x0, uint32_t& x1) {
    uint32_t ks2 = k0 ^ k1 ^ 0x1BD11BDAu;
#define TF_R(r) { x0 += x1; x1 = (x1 << (r)) | (x1 >> (32 - (r))); x1 ^= x0; }
    x0 += k0; x1 += k1;
    TF_R(13) TF_R(15) TF_R(26) TF_R(6)   x0 += k1;  x1 += ks2 + 1u;
    TF_R(17) TF_R(29) TF_R(16) TF_R(24)  x0 += ks2; x1 += k0  + 2u;
    TF_R(13) TF_R(15) TF_R(26) TF_R(6)   x0 += k0;  x1 += k1  + 3u;
    TF_R(17) TF_R(29) TF_R(16) TF_R(24)  x0 += k1;  x1 += ks2 + 4u;
    TF_R(13) TF_R(15) TF_R(26) TF_R(6)   x0 += ks2; x1 += k0  + 5u;
#undef TF_R
}

__device__ __forceinline__ bool drop_keep(uint32_t k0, uint32_t k1, uint32_t idx) {
    uint32_t x0 = 0u, x1 = idx;
    tf2x32(k0, k1, x0, x1);
    return ((x0 ^ x1) & 0x80000000u) == 0u;
}

// ---------------- graph prep ---------------------------------------------------
__global__ void k_zero() {
    int i = blockIdx.x * blockDim.x + threadIdx.x;
    if (i < N_NODES) { g_deg[i] = 0; g_cnt[i] = 0; }
    if (i < HID) g_colsum[i] = 0.f;
}

__global__ void k_deg(const int* __restrict__ dst) {
    int e = blockIdx.x * blockDim.x + threadIdx.x;
    if (e < N_EDGES) atomicAdd(&g_deg[dst[e]], 1);
}

// per-block inclusive scan of deg -> rowptr[i+1] (partial), block sums -> g_bsum
__global__ void k_scan1() {
    __shared__ int s[SCAN_B];
    int t = threadIdx.x, b = blockIdx.x;
    int i = b * SCAN_B + t;
    int v = (i < N_NODES) ? g_deg[i] : 0;
    s[t] = v;
    __syncthreads();
#pragma unroll
    for (int off = 1; off < SCAN_B; off <<= 1) {
        int add = (t >= off) ? s[t - off] : 0;
        __syncthreads();
        s[t] += add;
        __syncthreads();
    }
    if (i < N_NODES) g_rowptr[i + 1] = s[t];
    if (t == SCAN_B - 1) g_bsum[b] = s[t];
}

__global__ void k_scan2() {
    __shared__ int s[128];
    int t = threadIdx.x;
    int v = (t < NSCANB) ? g_bsum[t] : 0;
    s[t] = v;
    __syncthreads();
#pragma unroll
    for (int off = 1; off < 128; off <<= 1) {
        int add = (t >= off) ? s[t - off] : 0;
        __syncthreads();
        s[t] += add;
        __syncthreads();
    }
    if (t < NSCANB) g_boff[t] = s[t] - v;   // exclusive
}

__global__ void k_scan3() {
    int i = blockIdx.x * blockDim.x + threadIdx.x;
    if (i < N_NODES) {
        g_rowptr[i + 1] += g_boff[i >> 10];
        g_norm[i] = rsqrtf((float)(g_deg[i] + 1));
    }
    if (i == 0) g_rowptr[0] = 0;
}

__global__ void k_fill(const int* __restrict__ src, const int* __restrict__ dst) {
    int e = blockIdx.x * blockDim.x + threadIdx.x;
    if (e >= N_EDGES) return;
    int d = dst[e];
    int ofs = atomicAdd(&g_cnt[d], 1);
    g_csr[g_rowptr[d] + ofs] = src[e];
}

// ---------------- gemm1: g_t = (feat @ w1) * norm ------------------------------
// block 256 thr, tile 128 nodes x 64 cols, K chunks of 16, k-major sA.
__global__ __launch_bounds__(256) void k_gemm1(const float* __restrict__ feat,
                                               const float* __restrict__ w1) {
    __shared__ float sA[16][132];   // k-major, padded (528B row, 16B aligned)
    __shared__ float sB[16][64];
    int tid = threadIdx.x;
    int nb  = blockIdx.x * 128;
    int tx  = tid & 15;             // col/4
    int ty  = tid >> 4;             // node/8
    float acc[8][4] = {};
#pragma unroll
    for (int kc = 0; kc < 8; kc++) {
        // load sA: 128 nodes x 16 k, transposed
#pragma unroll
        for (int l = 0; l < 2; l++) {
            int idx = tid + l * 256;        // 0..511
            int nd  = idx >> 2;             // 0..127
            int kq  = idx & 3;              // float4 group within 16
            int gn  = nb + nd;
            float4 v = make_float4(0.f, 0.f, 0.f, 0.f);
            if (gn < N_NODES)
                v = *reinterpret_cast<const float4*>(&feat[(size_t)gn * IN_DIM + kc * 16 + kq * 4]);
            sA[kq * 4 + 0][nd] = v.x;
            sA[kq * 4 + 1][nd] = v.y;
            sA[kq * 4 + 2][nd] = v.z;
            sA[kq * 4 + 3][nd] = v.w;
        }
        // load sB: 16 k x 64 cols
        {
            int kk = tid >> 4, c4 = tid & 15;
            float4 v = *reinterpret_cast<const float4*>(&w1[(kc * 16 + kk) * HID + c4 * 4]);
            *reinterpret_cast<float4*>(&sB[kk][c4 * 4]) = v;
        }
        __syncthreads();
#pragma unroll
        for (int kk = 0; kk < 16; kk++) {
            float4 b  = *reinterpret_cast<float4*>(&sB[kk][tx * 4]);
            float4 a0 = *reinterpret_cast<float4*>(&sA[kk][ty * 8]);
            float4 a1 = *reinterpret_cast<float4*>(&sA[kk][ty * 8 + 4]);
            float av[8] = {a0.x, a0.y, a0.z, a0.w, a1.x, a1.y, a1.z, a1.w};
#pragma unroll
            for (int i = 0; i < 8; i++) {
                acc[i][0] += av[i] * b.x;
                acc[i][1] += av[i] * b.y;
                acc[i][2] += av[i] * b.z;
                acc[i][3] += av[i] * b.w;
            }
        }
        __syncthreads();
    }
#pragma unroll
    for (int i = 0; i < 8; i++) {
        int gn = nb + ty * 8 + i;
        if (gn < N_NODES) {
            float nm = g_norm[gn];
            float4 v = make_float4(acc[i][0] * nm, acc[i][1] * nm,
                                   acc[i][2] * nm, acc[i][3] * nm);
            *reinterpret_cast<float4*>(&g_t[(size_t)gn * HID + tx * 4]) = v;
        }
    }
}

// ---------------- gather: warp per dst node; self-loop = own row ----------------
// mode 1: fused fin1 epilogue (norm, relu, dropout, *norm). mode 0: raw sum.
__global__ void k_gather(const float* __restrict__ sbuf, float* __restrict__ obuf,
                         int mode, uint32_t k0, uint32_t k1) {
    int w = (blockIdx.x * blockDim.x + threadIdx.x) >> 5;
    if (w >= N_NODES) return;
    int lane = threadIdx.x & 31;
    int beg = g_rowptr[w], end = g_rowptr[w + 1];
    float2 acc = *reinterpret_cast<const float2*>(&sbuf[(size_t)w * HID + lane * 2]);
    for (int base = beg; base < end; base += 32) {
        int j = base + lane;
        int s = (j < end) ? g_csr[j] : 0;
        int cnt = min(32, end - base);
#pragma unroll 4
        for (int t = 0; t < cnt; t++) {
            int ss = __shfl_sync(0xffffffffu, s, t);
            float2 v = *reinterpret_cast<const float2*>(&sbuf[(size_t)ss * HID + lane * 2]);
            acc.x += v.x; acc.y += v.y;
        }
    }
    if (mode) {
        float nm = g_norm[w];
        acc.x = fmaxf(acc.x * nm, 0.f);
        acc.y = fmaxf(acc.y * nm, 0.f);
        uint32_t idx = (uint32_t)w * HID + (uint32_t)(lane * 2);
        acc.x = drop_keep(k0, k1, idx)     ? 2.f * acc.x : 0.f;
        acc.y = drop_keep(k0, k1, idx + 1) ? 2.f * acc.y : 0.f;
        acc.x *= nm; acc.y *= nm;
    }
    *reinterpret_cast<float2*>(&obuf[(size_t)w * HID + lane * 2]) = acc;
}

// ---------------- fin2: h2 = dropout(relu((agg2@w2)*norm)); column sums ---------
__global__ void k_fin2(const float* __restrict__ w2, uint32_t kb0, uint32_t kb1) {
    __shared__ float sW[64 * 64];
    __shared__ float sIn[8 * 64];
    __shared__ float sOut[8 * 64];
    int tid = threadIdx.x;
    int nb = blockIdx.x * 8;
#pragma unroll
    for (int l = 0; l < 8; l++) sW[tid + l * 512] = w2[tid + l * 512];
    sIn[tid] = g_agg2[(size_t)nb * HID + tid];
    __syncthreads();
    int ny = tid >> 6, c = tid & 63;
    const float* a = &sIn[ny * 64];
    float acc = 0.f;
#pragma unroll
    for (int k = 0; k < 64; k++) acc += a[k] * sW[k * 64 + c];
    int node = nb + ny;
    float v = fmaxf(acc * g_norm[node], 0.f);
    uint32_t idx = (uint32_t)node * HID + (uint32_t)c;
    v = drop_keep(kb0, kb1, idx) ? 2.f * v : 0.f;
    g_h2[(size_t)node * HID + c] = v;
    sOut[tid] = v;
    __syncthreads();
    if (ny == 0) {
        float s = 0.f;
#pragma unroll
        for (int l = 0; l < 8; l++) s += sOut[l * 64 + c];
        atomicAdd(&g_colsum[c], s);
    }
}

// ---------------- conv(mean) + bias ---------------------------------------------
__global__ void k_omean(const float* __restrict__ cw, const float* __restrict__ cb) {
    __shared__ float m[64];
    int t = threadIdx.x;
    if (t < 64) m[t] = g_colsum[t] * (1.f / (float)N_NODES);
    __syncthreads();
    if (t < CONVOUT) {
        int o = t / 62, jj = t % 62;
        g_omean[t] = cw[o * 3 + 0] * m[jj] + cw[o * 3 + 1] * m[jj + 1]
                   + cw[o * 3 + 2] * m[jj + 2] + cb[o];
    }
}

// ---------------- per-node conv + radius + clip ----------------------------------
__global__ void k_final(const float* __restrict__ cw, const float* __restrict__ cb,
                        const float* __restrict__ ref, float* __restrict__ out) {
    __shared__ float sO[CONVOUT];
    int tid = threadIdx.x;
    if (tid < CONVOUT) sO[tid] = g_omean[tid];
    __syncthreads();
    int lane = tid & 31, warp = tid >> 5;
    int node = blockIdx.x * 8 + warp;
    float w00 = cw[0], w01 = cw[1], w02 = cw[2];
    float w10 = cw[3], w11 = cw[4], w12 = cw[5];
    float b0 = cb[0], b1 = cb[1];
    const float* h = &g_h2[(size_t)node * HID];
    float acc = 0.f;
#pragma unroll
    for (int l = 0; l < 4; l++) {
        int j = lane * 4 + l;
        if (j < CONVOUT) {
            float y;
            if (j < 62) y = w00 * h[j] + w01 * h[j + 1] + w02 * h[j + 2] + b0;
            else { int jj = j - 62; y = w10 * h[jj] + w11 * h[jj + 1] + w12 * h[jj + 2] + b1; }
            float d = y - sO[j] + 1e-6f;
            acc += d * d;
        }
    }
#pragma unroll
    for (int o = 16; o; o >>= 1) acc += __shfl_xor_sync(0xffffffffu, acc, o);
    if (lane == 0) {
        float r = sqrtf(acc);
        out[node] = fminf(fmaxf(r - ref[0], 1e-4f), 0.9999f);
    }
    if (blockIdx.x == 0 && tid == 0) out[N_NODES] = ref[0];
}

// ---------------- launch ----------------------------------------------------------
extern "C" void kernel_launch(void* const* d_in, const int* in_sizes, int n_in,
                              void* d_out, int out_size) {
    const float* feat = (const float*)d_in[0];
    const float* w1   = (const float*)d_in[1];
    const float* w2   = (const float*)d_in[2];
    const float* cw   = (const float*)d_in[3];
    const float* cb   = (const float*)d_in[4];
    const float* ref  = (const float*)d_in[5];
    const int*   src  = (const int*)d_in[6];
    const int*   dst  = (const int*)d_in[7];
    float* out = (float*)d_out;

    // dropout keys: key(42) = (0,42); split -> threefry counters (0,0),(0,1)
    uint32_t ka0 = 0, ka1 = 0, kb0 = 0, kb1 = 1;
    tf2x32(0u, 42u, ka0, ka1);
    tf2x32(0u, 42u, kb0, kb1);

    float* t_ptr;   cudaGetSymbolAddress((void**)&t_ptr, g_t);
    float* h1_ptr;  cudaGetSymbolAddress((void**)&h1_ptr, g_h1);
    float* a2_ptr;  cudaGetSymbolAddress((void**)&a2_ptr, g_agg2);

    k_zero<<<(N_NODES + 255) / 256, 256>>>();
    k_deg<<<(N_EDGES + 255) / 256, 256>>>(dst);
    k_scan1<<<NSCANB, SCAN_B>>>();
    k_scan2<<<1, 128>>>();
    k_scan3<<<(N_NODES + 255) / 256, 256>>>();
    k_fill<<<(N_EDGES + 255) / 256, 256>>>(src, dst);
    k_gemm1<<<(N_NODES + 127) / 128, 256>>>(feat, w1);
    k_gather<<<(N_NODES * 32 + 255) / 256, 256>>>(t_ptr, h1_ptr, 1, ka0, ka1);
    k_gather<<<(N_NODES * 32 + 255) / 256, 256>>>(h1_ptr, a2_ptr, 0, 0u, 0u);
    k_fin2<<<N_NODES / 8, 512>>>(w2, kb0, kb1);
    k_omean<<<1, 128>>>(cw, cb);
    k_final<<<N_NODES / 8, 256>>>(cw, cb, ref, out);
}